// round 5
// baseline (speedup 1.0000x reference)
#include <cuda_runtime.h>
#include <math_constants.h>

#define VOCAB   512
#define MAXLEN  512
#define BATCH   128
#define NFEAT   (VOCAB + VOCAB * VOCAB + 2)   // 262658
#define NTHREADS 256                           // 2 positions per thread

__global__ __launch_bounds__(NTHREADS)
void ngram_logreg_kernel(const float4* __restrict__ x4,    // [B, 256] float4 = [B,512,2] f32
                         const int*    __restrict__ lengths,
                         const float*  __restrict__ W,     // [NFEAT]
                         const float*  __restrict__ bias,  // [1]
                         float*        __restrict__ out)   // [B]
{
    __shared__ float s_sum[NTHREADS / 32];
    __shared__ float s_max[NTHREADS / 32];

    const int b = blockIdx.x;
    const int t = threadIdx.x;

    // ---- front-batch all independent loads (len arrives concurrent with x) ----
    const int len = __ldg(&lengths[b]);
    const float wt = __ldg(&W[NFEAT - 2]);
    const float wl = __ldg(&W[NFEAT - 1]);
    const float bb = __ldg(bias);

    const float4* row = x4 + (size_t)b * (MAXLEN / 2);
    float4 v   = __ldg(&row[t]);                              // pos 2t (x,y), 2t+1 (z,w)
    // action at pos 2t+2; clamp index (t=255's value is always masked out below)
    float a2f  = __ldg((const float*)&row[(t < NTHREADS - 1) ? (t + 1) : t]);

    const int a0 = (int)v.x;
    const int a1 = (int)v.z;
    const int a2 = (int)a2f;

    const int p0 = 2 * t, p1 = 2 * t + 1, p2 = 2 * t + 2;
    const bool m0 = p0 < len;
    const bool m1 = p1 < len;
    const bool m2 = p2 < len;   // always false at t=255 (p2=512, len<=512)

    // ---- predicated gathers: dead positions issue NO memory traffic ----
    float sum = 0.0f;
    if (m0) sum += __ldg(&W[a0]);                             // unigram(2t)
    if (m1) sum += __ldg(&W[a1])                              // unigram(2t+1)
                 + __ldg(&W[VOCAB + a0 * VOCAB + a1]);        // bigram(2t,2t+1)
    if (m2) sum += __ldg(&W[VOCAB + a1 * VOCAB + a2]);        // bigram(2t+1,2t+2)

    float tmax = -CUDART_INF_F;
    if (m0) tmax = v.y;
    if (m1) tmax = fmaxf(tmax, v.w);

    // ---- block reduce ----
    #pragma unroll
    for (int off = 16; off > 0; off >>= 1) {
        sum  += __shfl_xor_sync(0xFFFFFFFFu, sum,  off);
        tmax  = fmaxf(tmax, __shfl_xor_sync(0xFFFFFFFFu, tmax, off));
    }
    const int wid = t >> 5;
    const int lid = t & 31;
    if (lid == 0) { s_sum[wid] = sum; s_max[wid] = tmax; }
    __syncthreads();

    if (t < 32) {
        sum  = (lid < NTHREADS / 32) ? s_sum[lid] : 0.0f;
        tmax = (lid < NTHREADS / 32) ? s_max[lid] : -CUDART_INF_F;
        #pragma unroll
        for (int off = 4; off > 0; off >>= 1) {
            sum  += __shfl_xor_sync(0xFFFFFFFFu, sum,  off);
            tmax  = fmaxf(tmax, __shfl_xor_sync(0xFFFFFFFFu, tmax, off));
        }
        if (lid == 0) {
            float total_time = (len > 0) ? tmax : 0.0f;       // len >= 1 per spec
            out[b] = sum + wt * total_time + wl * (float)len + bb;
        }
    }
}

extern "C" void kernel_launch(void* const* d_in, const int* in_sizes, int n_in,
                              void* d_out, int out_size)
{
    const float4* x       = (const float4*)d_in[0];  // [B, MAXLEN, 2] f32, 16B-aligned
    const int*    lengths = (const int*)   d_in[1];  // [B] int32
    const float*  W       = (const float*) d_in[2];  // [1, NFEAT] f32
    const float*  bias    = (const float*) d_in[3];  // [1] f32
    float*        out     = (float*)d_out;           // [B, 1] f32

    ngram_logreg_kernel<<<BATCH, NTHREADS>>>(x, lengths, W, bias, out);
}